// round 1
// baseline (speedup 1.0000x reference)
#include <cuda_runtime.h>

#define BB 4
#define NN 2048
#define HH 64
#define NHEAD 4
#define TOPK 10

// Scratch (device globals — no allocation in kernel_launch)
__device__ __align__(128) float g_q [(size_t)BB * NN * HH];
__device__ __align__(128) float g_kt[(size_t)BB * HH * NN];          // [b][j][n], j = head*16+d
__device__ __align__(128) float g_Asp[(size_t)BB * NN * NN];         // masked A_learn (A_sparse)

// ---------------------------------------------------------------------------
// Kernel A: encoders + fusion + Q/K projections. 1 warp = 1 node.
// ---------------------------------------------------------------------------
__global__ __launch_bounds__(256) void k_encode(
    const float* __restrict__ xd, const float* __restrict__ xs,
    const float* __restrict__ Wd, const float* __restrict__ bd,
    const float* __restrict__ Ws, const float* __restrict__ bs,
    const float* __restrict__ Wf, const float* __restrict__ bf,
    const float* __restrict__ Wq, const float* __restrict__ Wk)
{
    __shared__ float xm_s[8][16];
    __shared__ float cat_s[8][128];
    __shared__ float h_s[8][64];
    int tid = threadIdx.x, w = tid >> 5, l = tid & 31;
    int node = blockIdx.x * 8 + w;            // b*2048 + n

    // mean over T of x_dyn (affine commutes with mean)
    const float* xp = xd + (size_t)node * 512;
    if (l < 16) {
        float s = 0.f;
        #pragma unroll
        for (int t = 0; t < 32; ++t) s += xp[t * 16 + l];
        xm_s[w][l] = s * (1.0f / 32.0f);
    }
    __syncwarp();

    // temporal encoder: relu(xm @ W_dyn + b_dyn)
    float h1a = bd[l], h1b = bd[l + 32];
    #pragma unroll
    for (int d = 0; d < 16; ++d) {
        float x = xm_s[w][d];
        h1a += x * Wd[d * 64 + l];
        h1b += x * Wd[d * 64 + l + 32];
    }
    cat_s[w][l]      = fmaxf(h1a, 0.f);
    cat_s[w][l + 32] = fmaxf(h1b, 0.f);

    // static encoder: relu(x_stat @ W_stat + b_stat)
    float h2a = bs[l], h2b = bs[l + 32];
    const float* xsp = xs + (size_t)node * 8;
    #pragma unroll
    for (int d = 0; d < 8; ++d) {
        float x = xsp[d];
        h2a += x * Ws[d * 64 + l];
        h2b += x * Ws[d * 64 + l + 32];
    }
    cat_s[w][64 + l] = fmaxf(h2a, 0.f);
    cat_s[w][96 + l] = fmaxf(h2b, 0.f);
    __syncwarp();

    // fusion: concat @ W_fuse + b_fuse
    float ha = bf[l], hb = bf[l + 32];
    #pragma unroll 8
    for (int i = 0; i < 128; ++i) {
        float c = cat_s[w][i];
        ha += c * Wf[i * 64 + l];
        hb += c * Wf[i * 64 + l + 32];
    }
    h_s[w][l] = ha; h_s[w][l + 32] = hb;
    __syncwarp();

    // q = h@Wq, k = h@Wk
    float qa = 0.f, qb = 0.f, k1 = 0.f, k2 = 0.f;
    #pragma unroll 8
    for (int i = 0; i < 64; ++i) {
        float hv = h_s[w][i];
        qa += hv * Wq[i * 64 + l];
        qb += hv * Wq[i * 64 + l + 32];
        k1 += hv * Wk[i * 64 + l];
        k2 += hv * Wk[i * 64 + l + 32];
    }
    g_q[(size_t)node * 64 + l]      = qa;
    g_q[(size_t)node * 64 + l + 32] = qb;
    int b = node >> 11, n = node & 2047;
    g_kt[((size_t)b * 64 + l)      * 2048 + n] = k1;   // K stored [b][j][n]
    g_kt[((size_t)b * 64 + l + 32) * 2048 + n] = k2;
}

// ---------------------------------------------------------------------------
// Kernel B: scores -> per-head softmax (no max shift; scores sigma~0.13) ->
// head average -> per-row top-10 mask -> write A_sparse.
// 1 block = 8 rows; thread owns 8 consecutive m; K in registers (reused x8 rows).
// ---------------------------------------------------------------------------
__global__ __launch_bounds__(256, 1) void k_attn()
{
    extern __shared__ float smem[];
    float* Arow = smem;                 // 8*2048
    float* q_s  = smem + 8 * 2048;      // 512
    float* S_s  = q_s + 512;            // 4*8

    int tid = threadIdx.x, w = tid >> 5, l = tid & 31;
    int b  = blockIdx.x >> 8;
    int n0 = (blockIdx.x & 255) * 8;
    int m0 = w * 256 + l * 8;

    for (int i = tid; i < 512; i += 256)
        q_s[i] = g_q[((size_t)b * 2048 + n0 + (i >> 6)) * 64 + (i & 63)];
    if (tid < 32) S_s[tid] = 0.f;
    __syncthreads();

    float acc[64];
    #pragma unroll
    for (int i = 0; i < 64; ++i) acc[i] = 0.f;

    for (int h = 0; h < 4; ++h) {
        float sc[64];
        #pragma unroll
        for (int i = 0; i < 64; ++i) sc[i] = 0.f;

        const float* kbase = g_kt + ((size_t)b * 64 + h * 16) * 2048 + m0;
        #pragma unroll
        for (int dc = 0; dc < 2; ++dc) {
            float4 kv0[8], kv1[8];
            #pragma unroll
            for (int d = 0; d < 8; ++d) {
                const float4* p = (const float4*)(kbase + (size_t)(dc * 8 + d) * 2048);
                kv0[d] = p[0]; kv1[d] = p[1];
            }
            #pragma unroll
            for (int r = 0; r < 8; ++r) {
                #pragma unroll
                for (int d = 0; d < 8; ++d) {
                    float qv = q_s[r * 64 + h * 16 + dc * 8 + d];
                    sc[r*8+0] += qv * kv0[d].x; sc[r*8+1] += qv * kv0[d].y;
                    sc[r*8+2] += qv * kv0[d].z; sc[r*8+3] += qv * kv0[d].w;
                    sc[r*8+4] += qv * kv1[d].x; sc[r*8+5] += qv * kv1[d].y;
                    sc[r*8+6] += qv * kv1[d].z; sc[r*8+7] += qv * kv1[d].w;
                }
            }
        }
        // exp (scale 1/sqrt(dh)=0.25) + per-row partial sums
        float rs[8];
        #pragma unroll
        for (int r = 0; r < 8; ++r) {
            float s = 0.f;
            #pragma unroll
            for (int j = 0; j < 8; ++j) {
                float e = __expf(sc[r * 8 + j] * 0.25f);
                sc[r * 8 + j] = e; s += e;
            }
            rs[r] = s;
        }
        #pragma unroll
        for (int off = 16; off; off >>= 1) {
            #pragma unroll
            for (int r = 0; r < 8; ++r)
                rs[r] += __shfl_xor_sync(0xffffffffu, rs[r], off);
        }
        if (l == 0) {
            #pragma unroll
            for (int r = 0; r < 8; ++r) atomicAdd(&S_s[h * 8 + r], rs[r]);
        }
        __syncthreads();
        #pragma unroll
        for (int r = 0; r < 8; ++r) {
            float inv = 0.25f / S_s[h * 8 + r];   // 1/4 head average folded in
            #pragma unroll
            for (int j = 0; j < 8; ++j) acc[r * 8 + j] += sc[r * 8 + j] * inv;
        }
    }

    // redistribute rows into shared so warp w owns row w
    #pragma unroll
    for (int r = 0; r < 8; ++r) {
        float4* dst = (float4*)&Arow[r * 2048 + m0];
        dst[0] = make_float4(acc[r*8+0], acc[r*8+1], acc[r*8+2], acc[r*8+3]);
        dst[1] = make_float4(acc[r*8+4], acc[r*8+5], acc[r*8+6], acc[r*8+7]);
    }
    __syncthreads();

    // per-warp top-10 of row w (lexicographic-exclusion rescan, regs only)
    float v[64];
    #pragma unroll
    for (int i = 0; i < 64; ++i) v[i] = Arow[w * 2048 + i * 32 + l];

    float topv[TOPK]; int topi[TOPK];
    float lastv = 3.402823466e38f; int lasti = -1;
    #pragma unroll
    for (int t = 0; t < TOPK; ++t) {
        float bm = -1.f; int bi = 0x7fffffff;
        #pragma unroll
        for (int i = 0; i < 64; ++i) {
            int m = i * 32 + l;
            float x = v[i];
            bool excl = (x > lastv) || (x == lastv && m <= lasti);
            if (!excl && (x > bm || (x == bm && m < bi))) { bm = x; bi = m; }
        }
        #pragma unroll
        for (int off = 16; off; off >>= 1) {
            float ov = __shfl_xor_sync(0xffffffffu, bm, off);
            int   oi = __shfl_xor_sync(0xffffffffu, bi, off);
            if (ov > bm || (ov == bm && oi < bi)) { bm = ov; bi = oi; }
        }
        topv[t] = bm; topi[t] = bi;
        lastv = bm; lasti = bi;
    }

    // write masked row (zeros except top-10)
    size_t rowoff = ((size_t)b * 2048 + n0 + w) * 2048;
    #pragma unroll
    for (int i = 0; i < 64; ++i) {
        int m = i * 32 + l;
        float val = 0.f;
        #pragma unroll
        for (int t = 0; t < TOPK; ++t)
            if (topi[t] == m) val = topv[t];
        g_Asp[rowoff + m] = val;
    }
}

// ---------------------------------------------------------------------------
// Kernel C1: A_final = 0.3*prior + 0.35*(Asp + Asp^T); write A_final and L=-A_final.
// 64x64 tiles, transpose through shared (both reads coalesced).
// ---------------------------------------------------------------------------
__global__ __launch_bounds__(256) void k_blend(
    const float* __restrict__ prior, float* __restrict__ out)
{
    __shared__ float sh[64][65];
    int b = blockIdx.z, ti = blockIdx.y, tj = blockIdx.x;
    size_t base = (size_t)b * 2048 * 2048;
    int tid = threadIdx.x;
    for (int idx = tid; idx < 4096; idx += 256) {
        int r = idx >> 6, c = idx & 63;
        sh[r][c] = g_Asp[base + (size_t)(tj * 64 + r) * 2048 + ti * 64 + c];
    }
    __syncthreads();
    const size_t OFF = (size_t)BB * NN * NN;
    for (int idx = tid; idx < 4096; idx += 256) {
        int i = idx >> 6, j = idx & 63;
        size_t gi = base + (size_t)(ti * 64 + i) * 2048 + tj * 64 + j;
        float a  = g_Asp[gi];
        float p  = prior[gi];
        float af = 0.3f * p + 0.35f * (a + sh[j][i]);
        out[OFF + gi] = af;    // A_final
        out[gi]       = -af;   // L (diagonal fixed in k_diag)
    }
}

// ---------------------------------------------------------------------------
// Kernel C2: degree = rowsum(A_final); L[n][n] = degree - A_final[n][n].
// Deterministic (no atomics).
// ---------------------------------------------------------------------------
__global__ __launch_bounds__(256) void k_diag(float* __restrict__ out)
{
    __shared__ float red[256];
    const size_t OFF = (size_t)BB * NN * NN;
    int row = blockIdx.x;                 // b*2048 + n
    size_t rb = (size_t)row * 2048;
    int tid = threadIdx.x;
    float s = 0.f;
    for (int m = tid; m < 2048; m += 256) s += out[OFF + rb + m];
    red[tid] = s;
    __syncthreads();
    for (int o = 128; o; o >>= 1) {
        if (tid < o) red[tid] += red[tid + o];
        __syncthreads();
    }
    if (tid == 0) {
        int n = row & 2047;
        float af = out[OFF + rb + n];
        out[rb + n] = red[0] - af;
    }
}

// ---------------------------------------------------------------------------
extern "C" void kernel_launch(void* const* d_in, const int* in_sizes, int n_in,
                              void* d_out, int out_size)
{
    const float* xd = (const float*)d_in[0];   // x_dyn
    const float* xs = (const float*)d_in[1];   // x_stat
    const float* Ap = (const float*)d_in[2];   // A_prior
    const float* Wd = (const float*)d_in[3];
    const float* bd = (const float*)d_in[4];
    const float* Ws = (const float*)d_in[5];
    const float* bs = (const float*)d_in[6];
    const float* Wf = (const float*)d_in[7];
    const float* bf = (const float*)d_in[8];
    const float* Wq = (const float*)d_in[9];
    const float* Wk = (const float*)d_in[10];
    float* out = (float*)d_out;

    const int SMEM_B = (8 * 2048 + 512 + 32) * (int)sizeof(float);  // 67712
    cudaFuncSetAttribute(k_attn, cudaFuncAttributeMaxDynamicSharedMemorySize, SMEM_B);

    k_encode<<<1024, 256>>>(xd, xs, Wd, bd, Ws, bs, Wf, bf, Wq, Wk);
    k_attn<<<1024, 256, SMEM_B>>>();
    k_blend<<<dim3(32, 32, 4), 256>>>(Ap, out);
    k_diag<<<8192, 256>>>(out);
}

// round 2
// speedup vs baseline: 1.0911x; 1.0911x over previous
#include <cuda_runtime.h>

#define BB 4
#define NN 2048
#define HH 64
#define TOPK 10

typedef unsigned long long u64;

// Scratch (device globals — no allocation in kernel_launch)
__device__ __align__(128) float g_q [(size_t)BB * NN * HH];
__device__ __align__(128) float g_kt[(size_t)BB * HH * NN];      // [b][j][n]
__device__ __align__(128) float g_Asp[(size_t)BB * NN * NN];     // masked A_learn
__device__ __align__(128) float g_degp[(size_t)BB * 32 * NN];    // degree partials [b][tj][row]

__device__ __forceinline__ u64 fma2(u64 a, u64 b, u64 c) {
    u64 d;
    asm("fma.rn.f32x2 %0, %1, %2, %3;" : "=l"(d) : "l"(a), "l"(b), "l"(c));
    return d;
}
__device__ __forceinline__ u64 pack2(float x) {
    u64 d;
    asm("mov.b64 %0, {%1, %1};" : "=l"(d) : "f"(x));
    return d;
}
__device__ __forceinline__ u64 pack2p(float x, float y) {
    u64 d;
    asm("mov.b64 %0, {%1, %2};" : "=l"(d) : "f"(x), "f"(y));
    return d;
}
__device__ __forceinline__ void unpack2(float& x, float& y, u64 d) {
    asm("mov.b64 {%0, %1}, %2;" : "=f"(x), "=f"(y) : "l"(d));
}

// ---------------------------------------------------------------------------
// Kernel A: encoders + fusion + Q/K projections. 1 warp = 1 node.
// ---------------------------------------------------------------------------
__global__ __launch_bounds__(256) void k_encode(
    const float* __restrict__ xd, const float* __restrict__ xs,
    const float* __restrict__ Wd, const float* __restrict__ bd,
    const float* __restrict__ Ws, const float* __restrict__ bs,
    const float* __restrict__ Wf, const float* __restrict__ bf,
    const float* __restrict__ Wq, const float* __restrict__ Wk)
{
    __shared__ float xm_s[8][16];
    __shared__ float cat_s[8][128];
    __shared__ float h_s[8][64];
    int tid = threadIdx.x, w = tid >> 5, l = tid & 31;
    int node = blockIdx.x * 8 + w;            // b*2048 + n

    const float* xp = xd + (size_t)node * 512;
    if (l < 16) {
        float s = 0.f;
        #pragma unroll
        for (int t = 0; t < 32; ++t) s += xp[t * 16 + l];
        xm_s[w][l] = s * (1.0f / 32.0f);
    }
    __syncwarp();

    float h1a = bd[l], h1b = bd[l + 32];
    #pragma unroll
    for (int d = 0; d < 16; ++d) {
        float x = xm_s[w][d];
        h1a += x * Wd[d * 64 + l];
        h1b += x * Wd[d * 64 + l + 32];
    }
    cat_s[w][l]      = fmaxf(h1a, 0.f);
    cat_s[w][l + 32] = fmaxf(h1b, 0.f);

    float h2a = bs[l], h2b = bs[l + 32];
    const float* xsp = xs + (size_t)node * 8;
    #pragma unroll
    for (int d = 0; d < 8; ++d) {
        float x = xsp[d];
        h2a += x * Ws[d * 64 + l];
        h2b += x * Ws[d * 64 + l + 32];
    }
    cat_s[w][64 + l] = fmaxf(h2a, 0.f);
    cat_s[w][96 + l] = fmaxf(h2b, 0.f);
    __syncwarp();

    float ha = bf[l], hb = bf[l + 32];
    #pragma unroll 8
    for (int i = 0; i < 128; ++i) {
        float c = cat_s[w][i];
        ha += c * Wf[i * 64 + l];
        hb += c * Wf[i * 64 + l + 32];
    }
    h_s[w][l] = ha; h_s[w][l + 32] = hb;
    __syncwarp();

    float qa = 0.f, qb = 0.f, k1 = 0.f, k2 = 0.f;
    #pragma unroll 8
    for (int i = 0; i < 64; ++i) {
        float hv = h_s[w][i];
        qa += hv * Wq[i * 64 + l];
        qb += hv * Wq[i * 64 + l + 32];
        k1 += hv * Wk[i * 64 + l];
        k2 += hv * Wk[i * 64 + l + 32];
    }
    g_q[(size_t)node * 64 + l]      = qa;
    g_q[(size_t)node * 64 + l + 32] = qb;
    int b = node >> 11, n = node & 2047;
    g_kt[((size_t)b * 64 + l)      * 2048 + n] = k1;
    g_kt[((size_t)b * 64 + l + 32) * 2048 + n] = k2;
}

// ---------------------------------------------------------------------------
// Kernel B: QK^T via packed f32x2 FMA, per-head softmax (no max shift),
// head average accumulated in SHARED (permuted layout, conflict-free),
// per-row top-10 mask -> A_sparse.
// 1 block = 8 rows; 256 threads; thread owns 8 consecutive m-columns.
// Shared column layout: value for column m lives at p(m) = (m%8)*256 + m/8.
// ---------------------------------------------------------------------------
__global__ __launch_bounds__(256, 1) void k_attn()
{
    extern __shared__ float smem[];
    float* Arow = smem;                 // 8 * 2048 (permuted layout)
    float* q_s  = smem + 8 * 2048;      // 512  (pre-scaled by 0.25)
    float* red  = q_s + 512;            // 64
    float* S_s  = red + 64;             // 8

    int tid = threadIdx.x, w = tid >> 5, l = tid & 31;
    int b  = blockIdx.x >> 8;
    int n0 = (blockIdx.x & 255) * 8;
    int m0 = w * 256 + l * 8;

    for (int i = tid; i < 512; i += 256)
        q_s[i] = g_q[((size_t)b * 2048 + n0 + (i >> 6)) * 64 + (i & 63)] * 0.25f;
    __syncthreads();

    for (int h = 0; h < 4; ++h) {
        u64 sc2[32];
        #pragma unroll
        for (int i = 0; i < 32; ++i) sc2[i] = 0ull;

        const float* kbase = g_kt + ((size_t)b * 64 + h * 16) * 2048 + m0;
        #pragma unroll
        for (int dc = 0; dc < 2; ++dc) {
            u64 kv[32];
            #pragma unroll
            for (int d = 0; d < 8; ++d) {
                const ulonglong2* p = (const ulonglong2*)(kbase + (size_t)(dc * 8 + d) * 2048);
                ulonglong2 a = p[0], c = p[1];
                kv[d*4+0] = a.x; kv[d*4+1] = a.y; kv[d*4+2] = c.x; kv[d*4+3] = c.y;
            }
            #pragma unroll
            for (int r = 0; r < 8; ++r) {
                const float4* qp = (const float4*)&q_s[r * 64 + h * 16 + dc * 8];
                float4 q0 = qp[0], q1 = qp[1];
                float qa[8] = {q0.x, q0.y, q0.z, q0.w, q1.x, q1.y, q1.z, q1.w};
                #pragma unroll
                for (int d = 0; d < 8; ++d) {
                    u64 q2 = pack2(qa[d]);
                    sc2[r*4+0] = fma2(q2, kv[d*4+0], sc2[r*4+0]);
                    sc2[r*4+1] = fma2(q2, kv[d*4+1], sc2[r*4+1]);
                    sc2[r*4+2] = fma2(q2, kv[d*4+2], sc2[r*4+2]);
                    sc2[r*4+3] = fma2(q2, kv[d*4+3], sc2[r*4+3]);
                }
            }
        }

        // exp + per-row partial sums (q pre-scaled, so exp(sc) directly)
        float rs[8];
        #pragma unroll
        for (int r = 0; r < 8; ++r) {
            float s = 0.f;
            #pragma unroll
            for (int c = 0; c < 4; ++c) {
                float x, y; unpack2(x, y, sc2[r*4+c]);
                float e0 = __expf(x), e1 = __expf(y);
                sc2[r*4+c] = pack2p(e0, e1);
                s += e0 + e1;
            }
            rs[r] = s;
        }
        #pragma unroll
        for (int off = 16; off; off >>= 1) {
            #pragma unroll
            for (int r = 0; r < 8; ++r)
                rs[r] += __shfl_xor_sync(0xffffffffu, rs[r], off);
        }
        if (l == 0) {
            #pragma unroll
            for (int r = 0; r < 8; ++r) red[r * 8 + w] = rs[r];
        }
        __syncthreads();
        if (tid < 8) {                    // deterministic fixed-order sum
            float s = 0.f;
            #pragma unroll
            for (int ww = 0; ww < 8; ++ww) s += red[tid * 8 + ww];
            S_s[tid] = s;
        }
        __syncthreads();

        // accumulate into Arow (permuted layout, conflict-free st.32)
        #pragma unroll
        for (int r = 0; r < 8; ++r) {
            float inv = 0.25f / S_s[r];   // 1/4 head-average folded in
            float* base = &Arow[r * 2048 + w * 32 + l];
            #pragma unroll
            for (int c = 0; c < 4; ++c) {
                float e0, e1; unpack2(e0, e1, sc2[r*4+c]);
                if (h == 0) {
                    base[(2*c)   * 256] = e0 * inv;
                    base[(2*c+1) * 256] = e1 * inv;
                } else {
                    base[(2*c)   * 256] += e0 * inv;
                    base[(2*c+1) * 256] += e1 * inv;
                }
            }
        }
        __syncthreads();
    }

    // per-warp top-10 of row w (lexicographic-exclusion rescan over regs)
    float v[64];
    #pragma unroll
    for (int i = 0; i < 64; ++i) v[i] = Arow[w * 2048 + i * 32 + l];

    float topv[TOPK]; int topi[TOPK];
    float lastv = 3.402823466e38f; int lasti = -1;
    #pragma unroll
    for (int t = 0; t < TOPK; ++t) {
        float bm = -1.f; int bi = 0x7fffffff;
        #pragma unroll
        for (int i = 0; i < 64; ++i) {
            int p = i * 32 + l;
            int m = (p >> 8) + (p & 255) * 8;   // un-permute
            float x = v[i];
            bool excl = (x > lastv) || (x == lastv && m <= lasti);
            if (!excl && (x > bm || (x == bm && m < bi))) { bm = x; bi = m; }
        }
        #pragma unroll
        for (int off = 16; off; off >>= 1) {
            float ov = __shfl_xor_sync(0xffffffffu, bm, off);
            int   oi = __shfl_xor_sync(0xffffffffu, bi, off);
            if (ov > bm || (ov == bm && oi < bi)) { bm = ov; bi = oi; }
        }
        topv[t] = bm; topi[t] = bi;
        lastv = bm; lasti = bi;
    }

    // write masked row (coalesced over m)
    size_t rowoff = ((size_t)b * 2048 + n0 + w) * 2048;
    #pragma unroll
    for (int i = 0; i < 64; ++i) {
        int m = i * 32 + l;
        float val = 0.f;
        #pragma unroll
        for (int t = 0; t < TOPK; ++t)
            if (topi[t] == m) val = topv[t];
        g_Asp[rowoff + m] = val;
    }
}

// ---------------------------------------------------------------------------
// Kernel C1: symmetric tile pairs (ti<=tj): sym = Asp + Asp^T computed once;
// A_final = 0.3*prior + 0.35*sym for both (ti,tj) and (tj,ti) regions;
// writes A_final and L=-A_final plus deterministic per-tile row-sum partials.
// ---------------------------------------------------------------------------
__global__ __launch_bounds__(256) void k_blend(
    const float* __restrict__ prior, float* __restrict__ out)
{
    __shared__ float sh1[64][65];
    __shared__ float sh2[64][65];
    int b = blockIdx.z, ti = blockIdx.y, tj = blockIdx.x;
    if (ti > tj) return;
    size_t base = (size_t)b * 2048 * 2048;
    const size_t OFF = (size_t)BB * NN * NN;
    int tid = threadIdx.x;

    for (int idx = tid; idx < 4096; idx += 256) {
        int r = idx >> 6, c = idx & 63;
        sh1[r][c] = g_Asp[base + (size_t)(ti * 64 + r) * 2048 + tj * 64 + c];
        sh2[r][c] = g_Asp[base + (size_t)(tj * 64 + r) * 2048 + ti * 64 + c];
    }
    __syncthreads();

    // sym in place: sh1[i][j] = Asp(ti+i, tj+j) + Asp(tj+j, ti+i)
    for (int idx = tid; idx < 4096; idx += 256) {
        int i = idx >> 6, j = idx & 63;
        sh1[i][j] += sh2[j][i];
    }
    __syncthreads();

    // pass 1: region (ti rows, tj cols); af tile stored to sh2 for row sums
    for (int idx = tid; idx < 4096; idx += 256) {
        int i = idx >> 6, j = idx & 63;
        size_t gi = base + (size_t)(ti * 64 + i) * 2048 + tj * 64 + j;
        float af = 0.3f * prior[gi] + 0.35f * sh1[i][j];
        out[OFF + gi] = af;
        out[gi]       = -af;
        sh2[i][j] = af;
    }
    __syncthreads();
    if (tid < 64) {
        float s = 0.f;
        #pragma unroll 8
        for (int j = 0; j < 64; ++j) s += sh2[tid][j];
        g_degp[((size_t)b * 32 + tj) * 2048 + ti * 64 + tid] = s;
    }
    if (ti == tj) return;
    __syncthreads();

    // pass 2: region (tj rows, ti cols)
    for (int idx = tid; idx < 4096; idx += 256) {
        int jj = idx >> 6, ii = idx & 63;
        size_t gi = base + (size_t)(tj * 64 + jj) * 2048 + ti * 64 + ii;
        float af = 0.3f * prior[gi] + 0.35f * sh1[ii][jj];
        out[OFF + gi] = af;
        out[gi]       = -af;
        sh2[jj][ii] = af;
    }
    __syncthreads();
    if (tid < 64) {
        float s = 0.f;
        #pragma unroll 8
        for (int j = 0; j < 64; ++j) s += sh2[tid][j];
        g_degp[((size_t)b * 32 + ti) * 2048 + tj * 64 + tid] = s;
    }
}

// ---------------------------------------------------------------------------
// Kernel C2: combine 32 degree partials per row; fix L diagonal.
// ---------------------------------------------------------------------------
__global__ __launch_bounds__(256) void k_diag(float* __restrict__ out)
{
    const size_t OFF = (size_t)BB * NN * NN;
    int gid = blockIdx.x * 256 + threadIdx.x;   // 0..8191 = b*2048+n
    int b = gid >> 11, n = gid & 2047;
    float s = 0.f;
    #pragma unroll 8
    for (int t = 0; t < 32; ++t)
        s += g_degp[((size_t)b * 32 + t) * 2048 + n];
    size_t rb = (size_t)gid * 2048;
    float af = out[OFF + rb + n];
    out[rb + n] = s - af;
}

// ---------------------------------------------------------------------------
extern "C" void kernel_launch(void* const* d_in, const int* in_sizes, int n_in,
                              void* d_out, int out_size)
{
    const float* xd = (const float*)d_in[0];
    const float* xs = (const float*)d_in[1];
    const float* Ap = (const float*)d_in[2];
    const float* Wd = (const float*)d_in[3];
    const float* bd = (const float*)d_in[4];
    const float* Ws = (const float*)d_in[5];
    const float* bs = (const float*)d_in[6];
    const float* Wf = (const float*)d_in[7];
    const float* bf = (const float*)d_in[8];
    const float* Wq = (const float*)d_in[9];
    const float* Wk = (const float*)d_in[10];
    float* out = (float*)d_out;

    const int SMEM_B = (8 * 2048 + 512 + 64 + 8) * (int)sizeof(float);
    cudaFuncSetAttribute(k_attn, cudaFuncAttributeMaxDynamicSharedMemorySize, SMEM_B);

    k_encode<<<1024, 256>>>(xd, xs, Wd, bd, Ws, bs, Wf, bf, Wq, Wk);
    k_attn<<<1024, 256, SMEM_B>>>();
    k_blend<<<dim3(32, 32, 4), 256>>>(Ap, out);
    k_diag<<<32, 256>>>(out);
}

// round 3
// speedup vs baseline: 1.9766x; 1.8116x over previous
#include <cuda_runtime.h>

#define BB 4
#define NN 2048
#define TOPK 10

typedef unsigned long long u64;

// Scratch (device globals — no allocation in kernel_launch)
__device__ __align__(128) float g_q  [(size_t)BB * NN * 64];
__device__ __align__(128) float g_kt [(size_t)BB * 64 * NN];     // [b][j][n]
__device__ __align__(128) float g_Asp[(size_t)BB * NN * NN];     // masked A_learn
__device__ __align__(128) float g_degp[(size_t)BB * 32 * NN];    // degree partials

__device__ __forceinline__ u64 fma2(u64 a, u64 b, u64 c) {
    u64 d; asm("fma.rn.f32x2 %0, %1, %2, %3;" : "=l"(d) : "l"(a), "l"(b), "l"(c));
    return d;
}
__device__ __forceinline__ u64 mul2(u64 a, u64 b) {
    u64 d; asm("mul.rn.f32x2 %0, %1, %2;" : "=l"(d) : "l"(a), "l"(b));
    return d;
}
__device__ __forceinline__ u64 add2(u64 a, u64 b) {
    u64 d; asm("add.rn.f32x2 %0, %1, %2;" : "=l"(d) : "l"(a), "l"(b));
    return d;
}
__device__ __forceinline__ u64 pack2(float x) {
    u64 d; asm("mov.b64 %0, {%1, %1};" : "=l"(d) : "f"(x));
    return d;
}
__device__ __forceinline__ u64 pack2p(float x, float y) {
    u64 d; asm("mov.b64 %0, {%1, %2};" : "=l"(d) : "f"(x), "f"(y));
    return d;
}
__device__ __forceinline__ void unpack2(float& x, float& y, u64 d) {
    asm("mov.b64 {%0, %1}, %2;" : "=f"(x), "=f"(y) : "l"(d));
}

// ---------------------------------------------------------------------------
// Kernel A: encoders + fusion + Q/K projections. 1 warp = 1 node.
// ---------------------------------------------------------------------------
__global__ __launch_bounds__(256) void k_encode(
    const float* __restrict__ xd, const float* __restrict__ xs,
    const float* __restrict__ Wd, const float* __restrict__ bd,
    const float* __restrict__ Ws, const float* __restrict__ bs,
    const float* __restrict__ Wf, const float* __restrict__ bf,
    const float* __restrict__ Wq, const float* __restrict__ Wk)
{
    __shared__ float xm_s[8][16];
    __shared__ float cat_s[8][128];
    __shared__ float h_s[8][64];
    int tid = threadIdx.x, w = tid >> 5, l = tid & 31;
    int node = blockIdx.x * 8 + w;            // b*2048 + n

    // mean over T of x_dyn — all 32 lanes participate (2 lanes per feature)
    const float* xp = xd + (size_t)node * 512;
    {
        int dd = l & 15, hh = l >> 4;
        float s = 0.f;
        #pragma unroll
        for (int t = hh; t < 32; t += 2) s += xp[t * 16 + dd];
        s += __shfl_xor_sync(0xffffffffu, s, 16);
        if (l < 16) xm_s[w][l] = s * (1.0f / 32.0f);
    }
    __syncwarp();

    float h1a = bd[l], h1b = bd[l + 32];
    #pragma unroll
    for (int d = 0; d < 16; ++d) {
        float x = xm_s[w][d];
        h1a += x * Wd[d * 64 + l];
        h1b += x * Wd[d * 64 + l + 32];
    }
    cat_s[w][l]      = fmaxf(h1a, 0.f);
    cat_s[w][l + 32] = fmaxf(h1b, 0.f);

    float h2a = bs[l], h2b = bs[l + 32];
    const float* xsp = xs + (size_t)node * 8;
    #pragma unroll
    for (int d = 0; d < 8; ++d) {
        float x = xsp[d];
        h2a += x * Ws[d * 64 + l];
        h2b += x * Ws[d * 64 + l + 32];
    }
    cat_s[w][64 + l] = fmaxf(h2a, 0.f);
    cat_s[w][96 + l] = fmaxf(h2b, 0.f);
    __syncwarp();

    float ha = bf[l], hb = bf[l + 32];
    #pragma unroll 8
    for (int i = 0; i < 128; ++i) {
        float c = cat_s[w][i];
        ha += c * Wf[i * 64 + l];
        hb += c * Wf[i * 64 + l + 32];
    }
    h_s[w][l] = ha; h_s[w][l + 32] = hb;
    __syncwarp();

    float qa = 0.f, qb = 0.f, k1 = 0.f, k2 = 0.f;
    #pragma unroll 8
    for (int i = 0; i < 64; ++i) {
        float hv = h_s[w][i];
        qa += hv * Wq[i * 64 + l];
        qb += hv * Wq[i * 64 + l + 32];
        k1 += hv * Wk[i * 64 + l];
        k2 += hv * Wk[i * 64 + l + 32];
    }
    g_q[(size_t)node * 64 + l]      = qa;
    g_q[(size_t)node * 64 + l + 32] = qb;
    int b = node >> 11, n = node & 2047;
    g_kt[((size_t)b * 64 + l)      * 2048 + n] = k1;
    g_kt[((size_t)b * 64 + l + 32) * 2048 + n] = k2;
}

// ---------------------------------------------------------------------------
// Kernel B: 16 rows/block, 512 threads, thread owns 4 consecutive m.
// QK^T via fma.rn.f32x2 with K streamed per d-pair (no big K array in regs),
// q pre-packed/duplicated in shared (LDS.128 broadcast covers 2 d-steps),
// per-head softmax (no max shift), head average RMW'd into shared Arow,
// value-chain top-10 + threshold mask -> A_sparse.
// ---------------------------------------------------------------------------
__global__ __launch_bounds__(512, 1) void k_attn()
{
    extern __shared__ float smem[];
    float* Arow = smem;                          // 16*2048 floats
    u64*   q2s  = (u64*)(smem + 16 * 2048);      // 16 rows * 64 dims (dup-packed)
    float* red  = smem + 16 * 2048 + 2048;       // 16 rows * 16 warps
    float* Sinv = red + 256;                     // 16

    int tid = threadIdx.x, w = tid >> 5, l = tid & 31;
    int b  = blockIdx.x >> 7;
    int n0 = (blockIdx.x & 127) * 16;
    int m0 = tid * 4;

    // q: pre-scale by 1/sqrt(dh)=0.25 and pack duplicated for f32x2
    for (int i = tid; i < 1024; i += 512) {
        int r = i >> 6, j = i & 63;
        float qv = g_q[((size_t)(b * 2048 + n0 + r)) * 64 + j] * 0.25f;
        q2s[i] = pack2(qv);
    }
    __syncthreads();

    const float* kb0 = g_kt + ((size_t)b * 64) * 2048 + m0;

    #pragma unroll 1
    for (int h = 0; h < 4; ++h) {
        u64 sc2[32];
        #pragma unroll
        for (int i = 0; i < 32; ++i) sc2[i] = 0ull;

        const float* kbase = kb0 + (size_t)(h * 16) * 2048;
        #pragma unroll
        for (int dp = 0; dp < 8; ++dp) {
            ulonglong2 kv0 = *(const ulonglong2*)(kbase + (size_t)(2 * dp)     * 2048);
            ulonglong2 kv1 = *(const ulonglong2*)(kbase + (size_t)(2 * dp + 1) * 2048);
            #pragma unroll
            for (int r = 0; r < 16; ++r) {
                ulonglong2 q01 = *(const ulonglong2*)&q2s[r * 64 + h * 16 + 2 * dp];
                sc2[2*r]   = fma2(q01.x, kv0.x, sc2[2*r]);
                sc2[2*r+1] = fma2(q01.x, kv0.y, sc2[2*r+1]);
                sc2[2*r]   = fma2(q01.y, kv1.x, sc2[2*r]);
                sc2[2*r+1] = fma2(q01.y, kv1.y, sc2[2*r+1]);
            }
        }

        // exp + per-row partial sums (q pre-scaled, exp direct)
        float rs[16];
        #pragma unroll
        for (int r = 0; r < 16; ++r) {
            float x0, x1, x2, x3;
            unpack2(x0, x1, sc2[2*r]); unpack2(x2, x3, sc2[2*r+1]);
            x0 = __expf(x0); x1 = __expf(x1); x2 = __expf(x2); x3 = __expf(x3);
            sc2[2*r] = pack2p(x0, x1); sc2[2*r+1] = pack2p(x2, x3);
            rs[r] = (x0 + x1) + (x2 + x3);
        }
        #pragma unroll
        for (int off = 16; off; off >>= 1) {
            #pragma unroll
            for (int r = 0; r < 16; ++r)
                rs[r] += __shfl_xor_sync(0xffffffffu, rs[r], off);
        }
        if (l == 0) {
            #pragma unroll
            for (int r = 0; r < 16; ++r) red[r * 16 + w] = rs[r];
        }
        __syncthreads();
        if (tid < 16) {                           // deterministic fixed-order sum
            float s = 0.f;
            #pragma unroll
            for (int ww = 0; ww < 16; ++ww) s += red[tid * 16 + ww];
            Sinv[tid] = 0.25f / s;                // 1/4 head-average folded in
        }
        __syncthreads();

        // accumulate into Arow (packed RMW, conflict-free 128-bit)
        if (h == 0) {
            #pragma unroll
            for (int r = 0; r < 16; ++r) {
                u64 inv2 = pack2(Sinv[r]);
                ulonglong2 val;
                val.x = mul2(sc2[2*r],   inv2);
                val.y = mul2(sc2[2*r+1], inv2);
                *(ulonglong2*)&Arow[r * 2048 + m0] = val;
            }
        } else {
            #pragma unroll
            for (int r = 0; r < 16; ++r) {
                u64 inv2 = pack2(Sinv[r]);
                ulonglong2* ap = (ulonglong2*)&Arow[r * 2048 + m0];
                ulonglong2 cur = *ap;
                cur.x = add2(cur.x, mul2(sc2[2*r],   inv2));
                cur.y = add2(cur.y, mul2(sc2[2*r+1], inv2));
                *ap = cur;
            }
        }
        // no barrier needed: red/Sinv of next head are ordered by its own syncs
    }
    __syncthreads();

    // warp w: top-10 of row w via value-only max chain, then threshold mask
    float v[64];
    #pragma unroll
    for (int i = 0; i < 64; ++i) v[i] = Arow[w * 2048 + i * 32 + l];

    float lastv = 3.402823466e38f;
    #pragma unroll 1
    for (int t = 0; t < TOPK; ++t) {
        float bm = -1.f;
        #pragma unroll
        for (int i = 0; i < 64; ++i) {
            float x = v[i];
            bm = fmaxf(bm, x < lastv ? x : -1.f);
        }
        #pragma unroll
        for (int off = 16; off; off >>= 1)
            bm = fmaxf(bm, __shfl_xor_sync(0xffffffffu, bm, off));
        lastv = bm;
    }
    float thr = lastv;                            // 10th-largest value

    size_t rowoff = ((size_t)(b * 2048 + n0 + w)) * 2048;
    #pragma unroll
    for (int i = 0; i < 64; ++i) {
        float x = v[i];
        g_Asp[rowoff + i * 32 + l] = (x >= thr) ? x : 0.f;
    }
}

// ---------------------------------------------------------------------------
// Kernel C1: symmetric tile pairs (ti<=tj): sym computed once; writes A_final,
// L=-A_final, and deterministic per-tile degree partials.
// ---------------------------------------------------------------------------
__global__ __launch_bounds__(256) void k_blend(
    const float* __restrict__ prior, float* __restrict__ out)
{
    __shared__ float sh1[64][65];
    __shared__ float sh2[64][65];
    int b = blockIdx.z, ti = blockIdx.y, tj = blockIdx.x;
    if (ti > tj) return;
    size_t base = (size_t)b * 2048 * 2048;
    const size_t OFF = (size_t)BB * NN * NN;
    int tid = threadIdx.x;

    for (int idx = tid; idx < 4096; idx += 256) {
        int r = idx >> 6, c = idx & 63;
        sh1[r][c] = g_Asp[base + (size_t)(ti * 64 + r) * 2048 + tj * 64 + c];
        sh2[r][c] = g_Asp[base + (size_t)(tj * 64 + r) * 2048 + ti * 64 + c];
    }
    __syncthreads();

    for (int idx = tid; idx < 4096; idx += 256) {
        int i = idx >> 6, j = idx & 63;
        sh1[i][j] += sh2[j][i];
    }
    __syncthreads();

    for (int idx = tid; idx < 4096; idx += 256) {
        int i = idx >> 6, j = idx & 63;
        size_t gi = base + (size_t)(ti * 64 + i) * 2048 + tj * 64 + j;
        float af = 0.3f * prior[gi] + 0.35f * sh1[i][j];
        out[OFF + gi] = af;
        out[gi]       = -af;
        sh2[i][j] = af;
    }
    __syncthreads();
    if (tid < 64) {
        float s = 0.f;
        #pragma unroll 8
        for (int j = 0; j < 64; ++j) s += sh2[tid][j];
        g_degp[((size_t)b * 32 + tj) * 2048 + ti * 64 + tid] = s;
    }
    if (ti == tj) return;
    __syncthreads();

    for (int idx = tid; idx < 4096; idx += 256) {
        int jj = idx >> 6, ii = idx & 63;
        size_t gi = base + (size_t)(tj * 64 + jj) * 2048 + ti * 64 + ii;
        float af = 0.3f * prior[gi] + 0.35f * sh1[ii][jj];
        out[OFF + gi] = af;
        out[gi]       = -af;
        sh2[jj][ii] = af;
    }
    __syncthreads();
    if (tid < 64) {
        float s = 0.f;
        #pragma unroll 8
        for (int j = 0; j < 64; ++j) s += sh2[tid][j];
        g_degp[((size_t)b * 32 + ti) * 2048 + tj * 64 + tid] = s;
    }
}

// ---------------------------------------------------------------------------
// Kernel C2: combine 32 degree partials per row; fix L diagonal.
// ---------------------------------------------------------------------------
__global__ __launch_bounds__(256) void k_diag(float* __restrict__ out)
{
    const size_t OFF = (size_t)BB * NN * NN;
    int gid = blockIdx.x * 256 + threadIdx.x;   // b*2048+n
    int b = gid >> 11, n = gid & 2047;
    float s = 0.f;
    #pragma unroll 8
    for (int t = 0; t < 32; ++t)
        s += g_degp[((size_t)b * 32 + t) * 2048 + n];
    size_t rb = (size_t)gid * 2048;
    float af = out[OFF + rb + n];
    out[rb + n] = s - af;
}

// ---------------------------------------------------------------------------
extern "C" void kernel_launch(void* const* d_in, const int* in_sizes, int n_in,
                              void* d_out, int out_size)
{
    const float* xd = (const float*)d_in[0];
    const float* xs = (const float*)d_in[1];
    const float* Ap = (const float*)d_in[2];
    const float* Wd = (const float*)d_in[3];
    const float* bd = (const float*)d_in[4];
    const float* Ws = (const float*)d_in[5];
    const float* bs = (const float*)d_in[6];
    const float* Wf = (const float*)d_in[7];
    const float* bf = (const float*)d_in[8];
    const float* Wq = (const float*)d_in[9];
    const float* Wk = (const float*)d_in[10];
    float* out = (float*)d_out;

    const int SMEM_B = (16 * 2048 + 2048 + 256 + 16) * (int)sizeof(float); // 140352
    cudaFuncSetAttribute(k_attn, cudaFuncAttributeMaxDynamicSharedMemorySize, SMEM_B);

    k_encode<<<1024, 256>>>(xd, xs, Wd, bd, Ws, bs, Wf, bf, Wq, Wk);
    k_attn<<<512, 512, SMEM_B>>>();
    k_blend<<<dim3(32, 32, 4), 256>>>(Ap, out);
    k_diag<<<32, 256>>>(out);
}

// round 4
// speedup vs baseline: 2.3090x; 1.1682x over previous
#include <cuda_runtime.h>
#include <cuda_bf16.h>

#define BB 4
#define NN 2048
#define TOPK 10

typedef unsigned long long u64;
typedef unsigned int u32;

// Scratch (device globals — no allocation in kernel_launch)
__device__ __align__(128) float g_q  [(size_t)BB * NN * 64];
__device__ __align__(128) float g_k  [(size_t)BB * NN * 64];
__device__ __align__(128) float g_Asp[(size_t)BB * NN * NN];
__device__ __align__(128) float g_degp[(size_t)BB * 32 * NN];
// mma fragments: A (q) hi/lo: [b][rb(128)][h][lane] ; B (k): [b][h][NT(256)][lane]
__device__ __align__(128) uint4 g_qa_hi[4 * 128 * 4 * 32];
__device__ __align__(128) uint4 g_qa_lo[4 * 128 * 4 * 32];
__device__ __align__(128) uint4 g_kb  [4 * 4 * 256 * 32];

__device__ __forceinline__ void mma_bf16(float& d0, float& d1, float& d2, float& d3,
                                         u32 a0, u32 a1, u32 a2, u32 a3,
                                         u32 b0, u32 b1)
{
    asm volatile(
        "mma.sync.aligned.m16n8k16.row.col.f32.bf16.bf16.f32 "
        "{%0,%1,%2,%3},{%4,%5,%6,%7},{%8,%9},{%0,%1,%2,%3};"
        : "+f"(d0), "+f"(d1), "+f"(d2), "+f"(d3)
        : "r"(a0), "r"(a1), "r"(a2), "r"(a3), "r"(b0), "r"(b1));
}
__device__ __forceinline__ float ex2(float x) {
    float r; asm("ex2.approx.f32 %0, %1;" : "=f"(r) : "f"(x));
    return r;
}
__device__ __forceinline__ void bsplit(float x, unsigned short& h, unsigned short& l) {
    __nv_bfloat16 bh = __float2bfloat16(x);
    h = __bfloat16_as_ushort(bh);
    l = __bfloat16_as_ushort(__float2bfloat16(x - __bfloat162float(bh)));
}
__device__ __forceinline__ u32 pk(unsigned short a, unsigned short b) {
    return (u32)a | ((u32)b << 16);
}

// ---------------------------------------------------------------------------
// Kernel A: encoders + fusion + Q/K projections. 1 warp = 1 node.
// ---------------------------------------------------------------------------
__global__ __launch_bounds__(256) void k_encode(
    const float* __restrict__ xd, const float* __restrict__ xs,
    const float* __restrict__ Wd, const float* __restrict__ bd,
    const float* __restrict__ Ws, const float* __restrict__ bs,
    const float* __restrict__ Wf, const float* __restrict__ bf,
    const float* __restrict__ Wq, const float* __restrict__ Wk)
{
    __shared__ float xm_s[8][16];
    __shared__ float cat_s[8][128];
    __shared__ float h_s[8][64];
    int tid = threadIdx.x, w = tid >> 5, l = tid & 31;
    int node = blockIdx.x * 8 + w;

    const float* xp = xd + (size_t)node * 512;
    {
        int dd = l & 15, hh = l >> 4;
        float s = 0.f;
        #pragma unroll
        for (int t = hh; t < 32; t += 2) s += xp[t * 16 + dd];
        s += __shfl_xor_sync(0xffffffffu, s, 16);
        if (l < 16) xm_s[w][l] = s * (1.0f / 32.0f);
    }
    __syncwarp();

    float h1a = bd[l], h1b = bd[l + 32];
    #pragma unroll
    for (int d = 0; d < 16; ++d) {
        float x = xm_s[w][d];
        h1a += x * Wd[d * 64 + l];
        h1b += x * Wd[d * 64 + l + 32];
    }
    cat_s[w][l]      = fmaxf(h1a, 0.f);
    cat_s[w][l + 32] = fmaxf(h1b, 0.f);

    float h2a = bs[l], h2b = bs[l + 32];
    const float* xsp = xs + (size_t)node * 8;
    #pragma unroll
    for (int d = 0; d < 8; ++d) {
        float x = xsp[d];
        h2a += x * Ws[d * 64 + l];
        h2b += x * Ws[d * 64 + l + 32];
    }
    cat_s[w][64 + l] = fmaxf(h2a, 0.f);
    cat_s[w][96 + l] = fmaxf(h2b, 0.f);
    __syncwarp();

    float ha = bf[l], hb = bf[l + 32];
    #pragma unroll 8
    for (int i = 0; i < 128; ++i) {
        float c = cat_s[w][i];
        ha += c * Wf[i * 64 + l];
        hb += c * Wf[i * 64 + l + 32];
    }
    h_s[w][l] = ha; h_s[w][l + 32] = hb;
    __syncwarp();

    float qa = 0.f, qb = 0.f, k1 = 0.f, k2 = 0.f;
    #pragma unroll 8
    for (int i = 0; i < 64; ++i) {
        float hv = h_s[w][i];
        qa += hv * Wq[i * 64 + l];
        qb += hv * Wq[i * 64 + l + 32];
        k1 += hv * Wk[i * 64 + l];
        k2 += hv * Wk[i * 64 + l + 32];
    }
    g_q[(size_t)node * 64 + l]      = qa;
    g_q[(size_t)node * 64 + l + 32] = qb;
    g_k[(size_t)node * 64 + l]      = k1;
    g_k[(size_t)node * 64 + l + 32] = k2;
}

// ---------------------------------------------------------------------------
// Kernel A2: pack q/K into mma.sync m16n8k16 fragment order (bf16 hi/lo).
// q pre-scaled by 0.25*log2(e) so the MMA result feeds ex2 directly.
// ---------------------------------------------------------------------------
__global__ __launch_bounds__(256) void k_frag()
{
    int t = blockIdx.x * 256 + threadIdx.x;
    const float sc = 0.25f * 1.4426950408889634f;
    if (t < 65536) {
        // A fragment: t = ((b*128+rb)*4+h)*32+lane
        int lane = t & 31, h = (t >> 5) & 3, rb = (t >> 7) & 127, b = t >> 14;
        int g = lane >> 2, k0 = (lane & 3) * 2;
        int r0 = rb * 16 + g;
        const float* q0 = g_q + ((size_t)(b * 2048 + r0))     * 64 + h * 16;
        const float* q1 = g_q + ((size_t)(b * 2048 + r0 + 8)) * 64 + h * 16;
        unsigned short hh[8], ll[8];
        bsplit(q0[k0]     * sc, hh[0], ll[0]); bsplit(q0[k0 + 1] * sc, hh[1], ll[1]);
        bsplit(q1[k0]     * sc, hh[2], ll[2]); bsplit(q1[k0 + 1] * sc, hh[3], ll[3]);
        bsplit(q0[k0 + 8] * sc, hh[4], ll[4]); bsplit(q0[k0 + 9] * sc, hh[5], ll[5]);
        bsplit(q1[k0 + 8] * sc, hh[6], ll[6]); bsplit(q1[k0 + 9] * sc, hh[7], ll[7]);
        uint4 H, L;
        H.x = pk(hh[0], hh[1]); H.y = pk(hh[2], hh[3]);
        H.z = pk(hh[4], hh[5]); H.w = pk(hh[6], hh[7]);
        L.x = pk(ll[0], ll[1]); L.y = pk(ll[2], ll[3]);
        L.z = pk(ll[4], ll[5]); L.w = pk(ll[6], ll[7]);
        g_qa_hi[t] = H; g_qa_lo[t] = L;
    } else if (t < 65536 + 131072) {
        // B fragment: t2 = ((b*4+h)*256+NT)*32+lane
        int t2 = t - 65536;
        int lane = t2 & 31, NT = (t2 >> 5) & 255, h = (t2 >> 13) & 3, b = t2 >> 15;
        int n = NT * 8 + (lane >> 2), k0 = (lane & 3) * 2;
        const float* kp = g_k + ((size_t)(b * 2048 + n)) * 64 + h * 16;
        unsigned short hh[4], ll[4];
        bsplit(kp[k0],     hh[0], ll[0]); bsplit(kp[k0 + 1], hh[1], ll[1]);
        bsplit(kp[k0 + 8], hh[2], ll[2]); bsplit(kp[k0 + 9], hh[3], ll[3]);
        uint4 V;
        V.x = pk(hh[0], hh[1]); V.y = pk(hh[2], hh[3]);   // hi: k0..k1, k8..k9
        V.z = pk(ll[0], ll[1]); V.w = pk(ll[2], ll[3]);   // lo
        g_kb[t2] = V;
    }
}

// ---------------------------------------------------------------------------
// Kernel B: 16 rows/block, 512 threads. QK^T via mma.sync bf16 3-pass hi/lo,
// ex2 softmax (no max shift), head average into shared Arow (stride 2056),
// value-chain top-10 + threshold mask -> A_sparse.
// Warp w owns cols [w*128, (w+1)*128); acc tile t -> cols w*128+t*8+..
// ---------------------------------------------------------------------------
#define ASTRIDE 2056
__global__ __launch_bounds__(512, 1) void k_attn()
{
    extern __shared__ float smem[];
    float* Arow = smem;                          // 16 * 2056
    float* red  = smem + 16 * ASTRIDE;           // 16 rows * 16 warps
    float* Sinv = red + 256;                     // 16

    int tid = threadIdx.x, w = tid >> 5, l = tid & 31;
    int g = l >> 2, tig = l & 3;
    int b  = blockIdx.x >> 7;
    int rb = blockIdx.x & 127;
    int n0 = rb * 16;

    #pragma unroll 1
    for (int h = 0; h < 4; ++h) {
        uint4 AH = g_qa_hi[(((b * 128 + rb) * 4 + h) << 5) + l];
        uint4 AL = g_qa_lo[(((b * 128 + rb) * 4 + h) << 5) + l];

        float acc[64];
        #pragma unroll
        for (int i = 0; i < 64; ++i) acc[i] = 0.f;

        const uint4* kbp = g_kb + (((b * 4 + h) * 256 + w * 16) << 5) + l;
        #pragma unroll
        for (int t = 0; t < 16; ++t) {
            uint4 BV = kbp[t << 5];
            mma_bf16(acc[t*4], acc[t*4+1], acc[t*4+2], acc[t*4+3],
                     AH.x, AH.y, AH.z, AH.w, BV.x, BV.y);   // qh*kh
            mma_bf16(acc[t*4], acc[t*4+1], acc[t*4+2], acc[t*4+3],
                     AH.x, AH.y, AH.z, AH.w, BV.z, BV.w);   // qh*kl
            mma_bf16(acc[t*4], acc[t*4+1], acc[t*4+2], acc[t*4+3],
                     AL.x, AL.y, AL.z, AL.w, BV.x, BV.y);   // ql*kh
        }

        // exp2 + per-row partial sums
        float rs_lo = 0.f, rs_hi = 0.f;
        #pragma unroll
        for (int t = 0; t < 16; ++t) {
            float e0 = ex2(acc[t*4]),   e1 = ex2(acc[t*4+1]);
            float e2 = ex2(acc[t*4+2]), e3 = ex2(acc[t*4+3]);
            acc[t*4] = e0; acc[t*4+1] = e1; acc[t*4+2] = e2; acc[t*4+3] = e3;
            rs_lo += e0 + e1; rs_hi += e2 + e3;
        }
        rs_lo += __shfl_xor_sync(0xffffffffu, rs_lo, 1);
        rs_lo += __shfl_xor_sync(0xffffffffu, rs_lo, 2);
        rs_hi += __shfl_xor_sync(0xffffffffu, rs_hi, 1);
        rs_hi += __shfl_xor_sync(0xffffffffu, rs_hi, 2);
        if (tig == 0) {
            red[g * 16 + w]       = rs_lo;
            red[(g + 8) * 16 + w] = rs_hi;
        }
        __syncthreads();
        if (tid < 16) {                       // deterministic fixed-order sum
            float s = 0.f;
            #pragma unroll
            for (int ww = 0; ww < 16; ++ww) s += red[tid * 16 + ww];
            Sinv[tid] = 0.25f / s;            // 1/4 head-average folded in
        }
        __syncthreads();

        float inv_lo = Sinv[g], inv_hi = Sinv[g + 8];
        float2* A2 = (float2*)Arow;           // row stride 1028 float2
        if (h == 0) {
            #pragma unroll
            for (int t = 0; t < 16; ++t) {
                int c2 = w * 64 + t * 4 + tig;
                A2[g * 1028 + c2]       = make_float2(acc[t*4]   * inv_lo, acc[t*4+1] * inv_lo);
                A2[(g + 8) * 1028 + c2] = make_float2(acc[t*4+2] * inv_hi, acc[t*4+3] * inv_hi);
            }
        } else {
            #pragma unroll
            for (int t = 0; t < 16; ++t) {
                int c2 = w * 64 + t * 4 + tig;
                float2 lo = A2[g * 1028 + c2];
                float2 hi = A2[(g + 8) * 1028 + c2];
                lo.x += acc[t*4]   * inv_lo; lo.y += acc[t*4+1] * inv_lo;
                hi.x += acc[t*4+2] * inv_hi; hi.y += acc[t*4+3] * inv_hi;
                A2[g * 1028 + c2]       = lo;
                A2[(g + 8) * 1028 + c2] = hi;
            }
        }
        __syncthreads();
    }

    // warp w: top-10 of row w via value-only max chain, then threshold mask
    float v[64];
    #pragma unroll
    for (int i = 0; i < 64; ++i) v[i] = Arow[w * ASTRIDE + i * 32 + l];

    float lastv = 3.402823466e38f;
    #pragma unroll 1
    for (int t = 0; t < TOPK; ++t) {
        float bm = -1.f;
        #pragma unroll
        for (int i = 0; i < 64; ++i) {
            float x = v[i];
            bm = fmaxf(bm, x < lastv ? x : -1.f);
        }
        #pragma unroll
        for (int off = 16; off; off >>= 1)
            bm = fmaxf(bm, __shfl_xor_sync(0xffffffffu, bm, off));
        lastv = bm;
    }
    float thr = lastv;

    size_t rowoff = ((size_t)(b * 2048 + n0 + w)) * 2048;
    #pragma unroll
    for (int i = 0; i < 64; ++i) {
        float x = v[i];
        g_Asp[rowoff + i * 32 + l] = (x >= thr) ? x : 0.f;
    }
}

// ---------------------------------------------------------------------------
// Kernel C1: symmetric tile pairs (ti<=tj); writes A_final, L=-A_final, and
// deterministic per-tile degree partials.
// ---------------------------------------------------------------------------
__global__ __launch_bounds__(256) void k_blend(
    const float* __restrict__ prior, float* __restrict__ out)
{
    __shared__ float sh1[64][65];
    __shared__ float sh2[64][65];
    int b = blockIdx.z, ti = blockIdx.y, tj = blockIdx.x;
    if (ti > tj) return;
    size_t base = (size_t)b * 2048 * 2048;
    const size_t OFF = (size_t)BB * NN * NN;
    int tid = threadIdx.x;

    for (int idx = tid; idx < 4096; idx += 256) {
        int r = idx >> 6, c = idx & 63;
        sh1[r][c] = g_Asp[base + (size_t)(ti * 64 + r) * 2048 + tj * 64 + c];
        sh2[r][c] = g_Asp[base + (size_t)(tj * 64 + r) * 2048 + ti * 64 + c];
    }
    __syncthreads();

    for (int idx = tid; idx < 4096; idx += 256) {
        int i = idx >> 6, j = idx & 63;
        sh1[i][j] += sh2[j][i];
    }
    __syncthreads();

    for (int idx = tid; idx < 4096; idx += 256) {
        int i = idx >> 6, j = idx & 63;
        size_t gi = base + (size_t)(ti * 64 + i) * 2048 + tj * 64 + j;
        float af = 0.3f * prior[gi] + 0.35f * sh1[i][j];
        out[OFF + gi] = af;
        out[gi]       = -af;
        sh2[i][j] = af;
    }
    __syncthreads();
    if (tid < 64) {
        float s = 0.f;
        #pragma unroll 8
        for (int j = 0; j < 64; ++j) s += sh2[tid][j];
        g_degp[((size_t)b * 32 + tj) * 2048 + ti * 64 + tid] = s;
    }
    if (ti == tj) return;
    __syncthreads();

    for (int idx = tid; idx < 4096; idx += 256) {
        int jj = idx >> 6, ii = idx & 63;
        size_t gi = base + (size_t)(tj * 64 + jj) * 2048 + ti * 64 + ii;
        float af = 0.3f * prior[gi] + 0.35f * sh1[ii][jj];
        out[OFF + gi] = af;
        out[gi]       = -af;
        sh2[jj][ii] = af;
    }
    __syncthreads();
    if (tid < 64) {
        float s = 0.f;
        #pragma unroll 8
        for (int j = 0; j < 64; ++j) s += sh2[tid][j];
        g_degp[((size_t)b * 32 + ti) * 2048 + tj * 64 + tid] = s;
    }
}

// ---------------------------------------------------------------------------
// Kernel C2: combine 32 degree partials per row; fix L diagonal.
// ---------------------------------------------------------------------------
__global__ __launch_bounds__(256) void k_diag(float* __restrict__ out)
{
    const size_t OFF = (size_t)BB * NN * NN;
    int gid = blockIdx.x * 256 + threadIdx.x;
    int b = gid >> 11, n = gid & 2047;
    float s = 0.f;
    #pragma unroll 8
    for (int t = 0; t < 32; ++t)
        s += g_degp[((size_t)b * 32 + t) * 2048 + n];
    size_t rb = (size_t)gid * 2048;
    float af = out[OFF + rb + n];
    out[rb + n] = s - af;
}

// ---------------------------------------------------------------------------
extern "C" void kernel_launch(void* const* d_in, const int* in_sizes, int n_in,
                              void* d_out, int out_size)
{
    const float* xd = (const float*)d_in[0];
    const float* xs = (const float*)d_in[1];
    const float* Ap = (const float*)d_in[2];
    const float* Wd = (const float*)d_in[3];
    const float* bd = (const float*)d_in[4];
    const float* Ws = (const float*)d_in[5];
    const float* bs = (const float*)d_in[6];
    const float* Wf = (const float*)d_in[7];
    const float* bf = (const float*)d_in[8];
    const float* Wq = (const float*)d_in[9];
    const float* Wk = (const float*)d_in[10];
    float* out = (float*)d_out;

    const int SMEM_B = (16 * ASTRIDE + 256 + 16) * (int)sizeof(float);  // 132672
    cudaFuncSetAttribute(k_attn, cudaFuncAttributeMaxDynamicSharedMemorySize, SMEM_B);

    k_encode<<<1024, 256>>>(xd, xs, Wd, bd, Ws, bs, Wf, bf, Wq, Wk);
    k_frag<<<768, 256>>>();
    k_attn<<<512, 512, SMEM_B>>>();
    k_blend<<<dim3(32, 32, 4), 256>>>(Ap, out);
    k_diag<<<32, 256>>>(out);
}

// round 5
// speedup vs baseline: 2.9017x; 1.2567x over previous
#include <cuda_runtime.h>
#include <cuda_bf16.h>

#define BB 4
#define NN 2048
#define TOPK 10

typedef unsigned long long u64;
typedef unsigned int u32;

// Scratch (device globals — no allocation in kernel_launch)
__device__ __align__(128) float g_q  [(size_t)BB * NN * 64];
__device__ __align__(128) float g_k  [(size_t)BB * NN * 64];
__device__ __align__(128) float g_deg  [BB * NN];     // 0.3*rowsum(prior)
__device__ __align__(128) float g_degsp[BB * NN];     // sparse degree contributions
__device__ __align__(128) float g_spv[BB * NN * 16];  // sparse values
__device__ __align__(128) int   g_spi[BB * NN * 16];  // sparse col indices
__device__ __align__(128) int   g_spc[BB * NN];       // sparse counts
// mma fragments: A (q) hi/lo: [b][rb(128)][h][lane] ; B (k): [b][h][NT(256)][lane]
__device__ __align__(128) uint4 g_qa_hi[4 * 128 * 4 * 32];
__device__ __align__(128) uint4 g_qa_lo[4 * 128 * 4 * 32];
__device__ __align__(128) uint4 g_kb  [4 * 4 * 256 * 32];

__device__ __forceinline__ void mma_bf16(float& d0, float& d1, float& d2, float& d3,
                                         u32 a0, u32 a1, u32 a2, u32 a3,
                                         u32 b0, u32 b1)
{
    asm volatile(
        "mma.sync.aligned.m16n8k16.row.col.f32.bf16.bf16.f32 "
        "{%0,%1,%2,%3},{%4,%5,%6,%7},{%8,%9},{%0,%1,%2,%3};"
        : "+f"(d0), "+f"(d1), "+f"(d2), "+f"(d3)
        : "r"(a0), "r"(a1), "r"(a2), "r"(a3), "r"(b0), "r"(b1));
}
__device__ __forceinline__ float ex2(float x) {
    float r; asm("ex2.approx.f32 %0, %1;" : "=f"(r) : "f"(x));
    return r;
}
__device__ __forceinline__ void bsplit(float x, unsigned short& h, unsigned short& l) {
    __nv_bfloat16 bh = __float2bfloat16(x);
    h = __bfloat16_as_ushort(bh);
    l = __bfloat16_as_ushort(__float2bfloat16(x - __bfloat162float(bh)));
}
__device__ __forceinline__ u32 pk(unsigned short a, unsigned short b) {
    return (u32)a | ((u32)b << 16);
}

// ---------------------------------------------------------------------------
// Kernel A: encoders + fusion + Q/K projections. 1 warp = 1 node.
// ---------------------------------------------------------------------------
__global__ __launch_bounds__(256) void k_encode(
    const float* __restrict__ xd, const float* __restrict__ xs,
    const float* __restrict__ Wd, const float* __restrict__ bd,
    const float* __restrict__ Ws, const float* __restrict__ bs,
    const float* __restrict__ Wf, const float* __restrict__ bf,
    const float* __restrict__ Wq, const float* __restrict__ Wk)
{
    __shared__ float xm_s[8][16];
    __shared__ float cat_s[8][128];
    __shared__ float h_s[8][64];
    int tid = threadIdx.x, w = tid >> 5, l = tid & 31;
    int node = blockIdx.x * 8 + w;

    const float* xp = xd + (size_t)node * 512;
    {
        int dd = l & 15, hh = l >> 4;
        float s = 0.f;
        #pragma unroll
        for (int t = hh; t < 32; t += 2) s += xp[t * 16 + dd];
        s += __shfl_xor_sync(0xffffffffu, s, 16);
        if (l < 16) xm_s[w][l] = s * (1.0f / 32.0f);
    }
    __syncwarp();

    float h1a = bd[l], h1b = bd[l + 32];
    #pragma unroll
    for (int d = 0; d < 16; ++d) {
        float x = xm_s[w][d];
        h1a += x * Wd[d * 64 + l];
        h1b += x * Wd[d * 64 + l + 32];
    }
    cat_s[w][l]      = fmaxf(h1a, 0.f);
    cat_s[w][l + 32] = fmaxf(h1b, 0.f);

    float h2a = bs[l], h2b = bs[l + 32];
    const float* xsp = xs + (size_t)node * 8;
    #pragma unroll
    for (int d = 0; d < 8; ++d) {
        float x = xsp[d];
        h2a += x * Ws[d * 64 + l];
        h2b += x * Ws[d * 64 + l + 32];
    }
    cat_s[w][64 + l] = fmaxf(h2a, 0.f);
    cat_s[w][96 + l] = fmaxf(h2b, 0.f);
    __syncwarp();

    float ha = bf[l], hb = bf[l + 32];
    #pragma unroll 8
    for (int i = 0; i < 128; ++i) {
        float c = cat_s[w][i];
        ha += c * Wf[i * 64 + l];
        hb += c * Wf[i * 64 + l + 32];
    }
    h_s[w][l] = ha; h_s[w][l + 32] = hb;
    __syncwarp();

    float qa = 0.f, qb = 0.f, k1 = 0.f, k2 = 0.f;
    #pragma unroll 8
    for (int i = 0; i < 64; ++i) {
        float hv = h_s[w][i];
        qa += hv * Wq[i * 64 + l];
        qb += hv * Wq[i * 64 + l + 32];
        k1 += hv * Wk[i * 64 + l];
        k2 += hv * Wk[i * 64 + l + 32];
    }
    g_q[(size_t)node * 64 + l]      = qa;
    g_q[(size_t)node * 64 + l + 32] = qb;
    g_k[(size_t)node * 64 + l]      = k1;
    g_k[(size_t)node * 64 + l + 32] = k2;
}

// ---------------------------------------------------------------------------
// Kernel A2: pack q/K into mma.sync m16n8k16 fragment order (bf16 hi/lo).
// q pre-scaled by 0.25*log2(e) so the MMA result feeds ex2 directly.
// ---------------------------------------------------------------------------
__global__ __launch_bounds__(256) void k_frag()
{
    int t = blockIdx.x * 256 + threadIdx.x;
    const float sc = 0.25f * 1.4426950408889634f;
    if (t < 65536) {
        int lane = t & 31, h = (t >> 5) & 3, rb = (t >> 7) & 127, b = t >> 14;
        int g = lane >> 2, k0 = (lane & 3) * 2;
        int r0 = rb * 16 + g;
        const float* q0 = g_q + ((size_t)(b * 2048 + r0))     * 64 + h * 16;
        const float* q1 = g_q + ((size_t)(b * 2048 + r0 + 8)) * 64 + h * 16;
        unsigned short hh[8], ll[8];
        bsplit(q0[k0]     * sc, hh[0], ll[0]); bsplit(q0[k0 + 1] * sc, hh[1], ll[1]);
        bsplit(q1[k0]     * sc, hh[2], ll[2]); bsplit(q1[k0 + 1] * sc, hh[3], ll[3]);
        bsplit(q0[k0 + 8] * sc, hh[4], ll[4]); bsplit(q0[k0 + 9] * sc, hh[5], ll[5]);
        bsplit(q1[k0 + 8] * sc, hh[6], ll[6]); bsplit(q1[k0 + 9] * sc, hh[7], ll[7]);
        uint4 H, L;
        H.x = pk(hh[0], hh[1]); H.y = pk(hh[2], hh[3]);
        H.z = pk(hh[4], hh[5]); H.w = pk(hh[6], hh[7]);
        L.x = pk(ll[0], ll[1]); L.y = pk(ll[2], ll[3]);
        L.z = pk(ll[4], ll[5]); L.w = pk(ll[6], ll[7]);
        g_qa_hi[t] = H; g_qa_lo[t] = L;
    } else if (t < 65536 + 131072) {
        int t2 = t - 65536;
        int lane = t2 & 31, NT = (t2 >> 5) & 255, h = (t2 >> 13) & 3, b = t2 >> 15;
        int n = NT * 8 + (lane >> 2), k0 = (lane & 3) * 2;
        const float* kp = g_k + ((size_t)(b * 2048 + n)) * 64 + h * 16;
        unsigned short hh[4], ll[4];
        bsplit(kp[k0],     hh[0], ll[0]); bsplit(kp[k0 + 1], hh[1], ll[1]);
        bsplit(kp[k0 + 8], hh[2], ll[2]); bsplit(kp[k0 + 9], hh[3], ll[3]);
        uint4 V;
        V.x = pk(hh[0], hh[1]); V.y = pk(hh[2], hh[3]);
        V.z = pk(ll[0], ll[1]); V.w = pk(ll[2], ll[3]);
        g_kb[t2] = V;
    }
}

// ---------------------------------------------------------------------------
// Kernel B: 16 rows/block, 512 threads. QK^T via mma.sync bf16 3-pass hi/lo,
// ex2 softmax (no max shift), head average into shared Arow (stride 2056),
// value-chain top-10 -> compact sparse (idx,val) list per row.
// ---------------------------------------------------------------------------
#define ASTRIDE 2056
__global__ __launch_bounds__(512, 1) void k_attn()
{
    extern __shared__ float smem[];
    float* Arow = smem;                          // 16 * 2056
    float* red  = smem + 16 * ASTRIDE;           // 16 rows * 16 warps
    float* Sinv = red + 256;                     // 16
    __shared__ int scnt[16];

    int tid = threadIdx.x, w = tid >> 5, l = tid & 31;
    int g = l >> 2, tig = l & 3;
    int b  = blockIdx.x >> 7;
    int rb = blockIdx.x & 127;
    int n0 = rb * 16;

    #pragma unroll 1
    for (int h = 0; h < 4; ++h) {
        uint4 AH = g_qa_hi[(((b * 128 + rb) * 4 + h) << 5) + l];
        uint4 AL = g_qa_lo[(((b * 128 + rb) * 4 + h) << 5) + l];

        float acc[64];
        #pragma unroll
        for (int i = 0; i < 64; ++i) acc[i] = 0.f;

        const uint4* kbp = g_kb + (((b * 4 + h) * 256 + w * 16) << 5) + l;
        #pragma unroll
        for (int t = 0; t < 16; ++t) {
            uint4 BV = kbp[t << 5];
            mma_bf16(acc[t*4], acc[t*4+1], acc[t*4+2], acc[t*4+3],
                     AH.x, AH.y, AH.z, AH.w, BV.x, BV.y);
            mma_bf16(acc[t*4], acc[t*4+1], acc[t*4+2], acc[t*4+3],
                     AH.x, AH.y, AH.z, AH.w, BV.z, BV.w);
            mma_bf16(acc[t*4], acc[t*4+1], acc[t*4+2], acc[t*4+3],
                     AL.x, AL.y, AL.z, AL.w, BV.x, BV.y);
        }

        float rs_lo = 0.f, rs_hi = 0.f;
        #pragma unroll
        for (int t = 0; t < 16; ++t) {
            float e0 = ex2(acc[t*4]),   e1 = ex2(acc[t*4+1]);
            float e2 = ex2(acc[t*4+2]), e3 = ex2(acc[t*4+3]);
            acc[t*4] = e0; acc[t*4+1] = e1; acc[t*4+2] = e2; acc[t*4+3] = e3;
            rs_lo += e0 + e1; rs_hi += e2 + e3;
        }
        rs_lo += __shfl_xor_sync(0xffffffffu, rs_lo, 1);
        rs_lo += __shfl_xor_sync(0xffffffffu, rs_lo, 2);
        rs_hi += __shfl_xor_sync(0xffffffffu, rs_hi, 1);
        rs_hi += __shfl_xor_sync(0xffffffffu, rs_hi, 2);
        if (tig == 0) {
            red[g * 16 + w]       = rs_lo;
            red[(g + 8) * 16 + w] = rs_hi;
        }
        __syncthreads();
        if (tid < 16) {
            float s = 0.f;
            #pragma unroll
            for (int ww = 0; ww < 16; ++ww) s += red[tid * 16 + ww];
            Sinv[tid] = 0.25f / s;
        }
        __syncthreads();

        float inv_lo = Sinv[g], inv_hi = Sinv[g + 8];
        float2* A2 = (float2*)Arow;
        if (h == 0) {
            #pragma unroll
            for (int t = 0; t < 16; ++t) {
                int c2 = w * 64 + t * 4 + tig;
                A2[g * 1028 + c2]       = make_float2(acc[t*4]   * inv_lo, acc[t*4+1] * inv_lo);
                A2[(g + 8) * 1028 + c2] = make_float2(acc[t*4+2] * inv_hi, acc[t*4+3] * inv_hi);
            }
        } else {
            #pragma unroll
            for (int t = 0; t < 16; ++t) {
                int c2 = w * 64 + t * 4 + tig;
                float2 lo = A2[g * 1028 + c2];
                float2 hi = A2[(g + 8) * 1028 + c2];
                lo.x += acc[t*4]   * inv_lo; lo.y += acc[t*4+1] * inv_lo;
                hi.x += acc[t*4+2] * inv_hi; hi.y += acc[t*4+3] * inv_hi;
                A2[g * 1028 + c2]       = lo;
                A2[(g + 8) * 1028 + c2] = hi;
            }
        }
        __syncthreads();
    }

    if (tid < 16) scnt[tid] = 0;

    // warp w: top-10 of row w via value-only max chain
    float v[64];
    #pragma unroll
    for (int i = 0; i < 64; ++i) v[i] = Arow[w * ASTRIDE + i * 32 + l];

    float lastv = 3.402823466e38f;
    #pragma unroll 1
    for (int t = 0; t < TOPK; ++t) {
        float bm = -1.f;
        #pragma unroll
        for (int i = 0; i < 64; ++i) {
            float x = v[i];
            bm = fmaxf(bm, x < lastv ? x : -1.f);
        }
        #pragma unroll
        for (int off = 16; off; off >>= 1)
            bm = fmaxf(bm, __shfl_xor_sync(0xffffffffu, bm, off));
        lastv = bm;
    }
    float thr = lastv;                 // 10th-largest value
    __syncthreads();                   // scnt init visible to all warps

    // emit compact sparse list (values >= thr)
    int row = b * 2048 + n0 + w;
    #pragma unroll
    for (int i = 0; i < 64; ++i) {
        float x = v[i];
        if (x >= thr) {
            int p = atomicAdd(&scnt[w], 1);
            if (p < 16) {
                g_spv[row * 16 + p] = x;
                g_spi[row * 16 + p] = i * 32 + l;
            }
        }
    }
    __syncwarp();
    if (l == 0) g_spc[row] = min(scnt[w], 16);
}

// ---------------------------------------------------------------------------
// Kernel C1: pure stream. af = 0.3*prior -> A_final and L=-af; degree partial
// = 0.3*rowsum(prior). One block per row, fully coalesced.
// ---------------------------------------------------------------------------
__global__ __launch_bounds__(256) void k_blend(
    const float* __restrict__ prior, float* __restrict__ out)
{
    __shared__ float red[8];
    int row = blockIdx.x;                 // b*2048 + n
    size_t rb = (size_t)row * 2048;
    const size_t OFF = (size_t)BB * NN * NN;
    int tid = threadIdx.x, w = tid >> 5, l = tid & 31;

    const float4* p4 = (const float4*)(prior + rb);
    float4* oA = (float4*)(out + OFF + rb);
    float4* oL = (float4*)(out + rb);

    float s = 0.f;
    #pragma unroll
    for (int i = 0; i < 2; ++i) {
        int c = tid + i * 256;
        float4 p = p4[c];
        float4 af = make_float4(0.3f * p.x, 0.3f * p.y, 0.3f * p.z, 0.3f * p.w);
        oA[c] = af;
        oL[c] = make_float4(-af.x, -af.y, -af.z, -af.w);
        s += (af.x + af.y) + (af.z + af.w);
    }
    #pragma unroll
    for (int off = 16; off; off >>= 1)
        s += __shfl_xor_sync(0xffffffffu, s, off);
    if (l == 0) red[w] = s;
    __syncthreads();
    if (tid == 0) {
        float t = 0.f;
        #pragma unroll
        for (int i = 0; i < 8; ++i) t += red[i];
        g_deg[row]   = t;
        g_degsp[row] = 0.f;
    }
}

// ---------------------------------------------------------------------------
// Kernel C2: scatter sparse symmetric contributions into A_final, L, degree.
// ---------------------------------------------------------------------------
__global__ __launch_bounds__(256) void k_scatter(float* __restrict__ out)
{
    int t = blockIdx.x * 256 + threadIdx.x;      // 131072 = 8192 rows * 16
    int row = t >> 4, slot = t & 15;
    if (slot >= g_spc[row]) return;
    int b = row >> 11, n = row & 2047;
    float v = 0.35f * g_spv[row * 16 + slot];
    int m = g_spi[row * 16 + slot];
    size_t base = (size_t)b * 2048 * 2048;
    const size_t OFF = (size_t)BB * NN * NN;
    atomicAdd(&out[OFF + base + (size_t)n * 2048 + m],  v);
    atomicAdd(&out[OFF + base + (size_t)m * 2048 + n],  v);
    atomicAdd(&out[base + (size_t)n * 2048 + m], -v);
    atomicAdd(&out[base + (size_t)m * 2048 + n], -v);
    atomicAdd(&g_degsp[row], v);
    atomicAdd(&g_degsp[(b << 11) + m], v);
}

// ---------------------------------------------------------------------------
// Kernel C3: L[n][n] = degree - A_final[n][n].
// ---------------------------------------------------------------------------
__global__ __launch_bounds__(256) void k_diag(float* __restrict__ out)
{
    const size_t OFF = (size_t)BB * NN * NN;
    int gid = blockIdx.x * 256 + threadIdx.x;    // b*2048+n
    int n = gid & 2047;
    float deg = g_deg[gid] + g_degsp[gid];
    size_t rb = (size_t)gid * 2048;
    float af = out[OFF + rb + n];
    out[rb + n] = deg - af;
}

// ---------------------------------------------------------------------------
extern "C" void kernel_launch(void* const* d_in, const int* in_sizes, int n_in,
                              void* d_out, int out_size)
{
    const float* xd = (const float*)d_in[0];
    const float* xs = (const float*)d_in[1];
    const float* Ap = (const float*)d_in[2];
    const float* Wd = (const float*)d_in[3];
    const float* bd = (const float*)d_in[4];
    const float* Ws = (const float*)d_in[5];
    const float* bs = (const float*)d_in[6];
    const float* Wf = (const float*)d_in[7];
    const float* bf = (const float*)d_in[8];
    const float* Wq = (const float*)d_in[9];
    const float* Wk = (const float*)d_in[10];
    float* out = (float*)d_out;

    const int SMEM_B = (16 * ASTRIDE + 256 + 16) * (int)sizeof(float);  // 132672
    cudaFuncSetAttribute(k_attn, cudaFuncAttributeMaxDynamicSharedMemorySize, SMEM_B);

    k_encode<<<1024, 256>>>(xd, xs, Wd, bd, Ws, bs, Wf, bf, Wq, Wk);
    k_frag<<<768, 256>>>();
    k_blend<<<8192, 256>>>(Ap, out);
    k_attn<<<512, 512, SMEM_B>>>();
    k_scatter<<<512, 256>>>(out);
    k_diag<<<32, 256>>>(out);
}